// round 12
// baseline (speedup 1.0000x reference)
#include <cuda_runtime.h>
#include <cuda_bf16.h>
#include <cuda_fp16.h>
#include <math.h>
#include <cstdint>

#define NN 100000
#define HID 128
#define NE 1600000
#define NC 10

// ---------------- scratch (device globals; no allocation allowed) -------------
__device__ int    g_cnt[NN];
__device__ int    g_rowptr[NN];
__device__ int    g_col[NE];
__device__ int    g_pos[NE];                   // intra-segment position per edge
__device__ int    g_blockSums[256];
__device__ __half g_bufH1[(size_t)NN * HID];   // layer-1 h' = invs*h (fp16)
__device__ __half g_bufH2[(size_t)NN * HID];   // layer-2 h' (fp16)
// bf16 hi/lo weight images, layout [n][k/2] u32 pairs
__device__ uint32_t g_W1hi[128 * 64];
__device__ uint32_t g_W1lo[128 * 64];
__device__ uint32_t g_W2hi[128 * 64];
__device__ uint32_t g_W2lo[128 * 64];

__device__ __forceinline__ uint32_t smem_u32(const void* p) {
    uint32_t a;
    asm("{ .reg .u64 t; cvta.to.shared.u64 t, %1; cvt.u32.u64 %0, t; }" : "=r"(a) : "l"(p));
    return a;
}

// ---------------- degree histogram + position record (single atomic pass) ----
__global__ void k_count(const int* __restrict__ dst) {
    int e4 = blockIdx.x * blockDim.x + threadIdx.x;
    if (e4 < NE / 4) {
        int4 d = ((const int4*)dst)[e4];
        int4 p;
        p.x = atomicAdd(&g_cnt[d.x], 1);
        p.y = atomicAdd(&g_cnt[d.y], 1);
        p.z = atomicAdd(&g_cnt[d.z], 1);
        p.w = atomicAdd(&g_cnt[d.w], 1);
        ((int4*)g_pos)[e4] = p;
    }
}

// ---------------- exclusive scan (3-phase) ----------------
__global__ void k_scanA() {
    __shared__ int s[512];
    int i = blockIdx.x * 512 + threadIdx.x;
    int v = (i < NN) ? g_cnt[i] : 0;
    s[threadIdx.x] = v;
    __syncthreads();
    #pragma unroll
    for (int off = 1; off < 512; off <<= 1) {
        int t = (threadIdx.x >= off) ? s[threadIdx.x - off] : 0;
        __syncthreads();
        s[threadIdx.x] += t;
        __syncthreads();
    }
    if (i < NN) g_rowptr[i] = s[threadIdx.x] - v;        // exclusive
    if (threadIdx.x == 511) g_blockSums[blockIdx.x] = s[511];
}

__global__ void k_scanB(int nblocks) {
    __shared__ int s[256];
    int t = threadIdx.x;
    int v = (t < nblocks) ? g_blockSums[t] : 0;
    s[t] = v;
    __syncthreads();
    #pragma unroll
    for (int off = 1; off < 256; off <<= 1) {
        int u = (t >= off) ? s[t - off] : 0;
        __syncthreads();
        s[t] += u;
        __syncthreads();
    }
    if (t < nblocks) g_blockSums[t] = s[t] - v;           // exclusive
}

__global__ void k_scanC() {
    int i = blockIdx.x * 512 + threadIdx.x;
    if (i < NN) g_rowptr[i] += g_blockSums[blockIdx.x];
}

// ---------------- CSR place (no atomics) ----------------
__global__ void k_place(const int* __restrict__ src, const int* __restrict__ dst) {
    int e4 = blockIdx.x * blockDim.x + threadIdx.x;
    if (e4 < NE / 4) {
        int4 s = ((const int4*)src)[e4];
        int4 d = ((const int4*)dst)[e4];
        int4 p = ((const int4*)g_pos)[e4];
        g_col[g_rowptr[d.x] + p.x] = s.x;
        g_col[g_rowptr[d.y] + p.y] = s.y;
        g_col[g_rowptr[d.z] + p.z] = s.z;
        g_col[g_rowptr[d.w] + p.w] = s.w;
    }
}

// ---------------- weight image precompute ----------------
__global__ void k_wimg(const float* __restrict__ W, int layer) {
    uint32_t* hiImg = (layer == 0 ? g_W1hi : g_W2hi);
    uint32_t* loImg = (layer == 0 ? g_W1lo : g_W2lo);
    int idx = blockIdx.x * blockDim.x + threadIdx.x;      // 0..8191 (pairs)
    if (idx >= 128 * 64) return;
    int n = idx >> 6, cp = idx & 63;
    int k0 = 2 * cp;
    float w0 = W[(size_t)k0 * HID + n];
    float w1 = W[(size_t)(k0 + 1) * HID + n];
    __nv_bfloat16 h0 = __float2bfloat16(w0), h1 = __float2bfloat16(w1);
    __nv_bfloat16 l0 = __float2bfloat16(w0 - __bfloat162float(h0));
    __nv_bfloat16 l1 = __float2bfloat16(w1 - __bfloat162float(h1));
    hiImg[idx] = (uint32_t)__bfloat16_as_ushort(h0) | ((uint32_t)__bfloat16_as_ushort(h1) << 16);
    loImg[idx] = (uint32_t)__bfloat16_as_ushort(l0) | ((uint32_t)__bfloat16_as_ushort(l1) << 16);
}

// ---------------- shared GEMM pieces -----------------------------------------
#define ROWW 68
#define MAT_A (64 * ROWW)                  // 4352 words
#define OFF_WHI (2 * MAT_A)                // 8704 words
#define OFF_WLO (OFF_WHI + 128 * ROWW)     // 17408 words
#define DSMEM_SZ ((OFF_WLO + 128 * ROWW) * 4)   // 104448 bytes

__device__ __forceinline__ void mma_bf16(float* d, uint32_t a0, uint32_t a1,
                                         uint32_t a2, uint32_t a3,
                                         uint32_t b0, uint32_t b1) {
    asm volatile(
        "mma.sync.aligned.m16n8k16.row.col.f32.bf16.bf16.f32 "
        "{%0,%1,%2,%3}, {%4,%5,%6,%7}, {%8,%9}, {%0,%1,%2,%3};\n"
        : "+f"(d[0]), "+f"(d[1]), "+f"(d[2]), "+f"(d[3])
        : "r"(a0), "r"(a1), "r"(a2), "r"(a3), "r"(b0), "r"(b1));
}

__device__ __forceinline__ void ldsm_x4(uint32_t& r0, uint32_t& r1, uint32_t& r2,
                                        uint32_t& r3, uint32_t addr) {
    asm volatile("ldmatrix.sync.aligned.m8n8.x4.shared.b16 {%0,%1,%2,%3}, [%4];"
                 : "=r"(r0), "=r"(r1), "=r"(r2), "=r"(r3) : "r"(addr));
}

// Phase-2 mainloop + epilogue (A/W tiles already staged in smem)
__device__ __forceinline__ void gemm_core(uint32_t* sm, int blockRow, __half* outH,
                                          int wid, int lane) {
    int g = lane >> 2, t = lane & 3;
    int rowGrp = wid & 3, nHalf = wid >> 2;

    float acc[8][4];
    #pragma unroll
    for (int j = 0; j < 8; j++)
        #pragma unroll
        for (int q = 0; q < 4; q++) acc[j][q] = 0.f;

    int grp = lane >> 3, l8 = lane & 7;
    uint32_t base = smem_u32(sm);
    uint32_t aOff = (uint32_t)((rowGrp * 16 + (grp & 1) * 8 + l8) * ROWW + (grp >> 1) * 4) * 4;
    uint32_t aHiAddr = base + aOff;
    uint32_t aLoAddr = base + MAT_A * 4 + aOff;
    uint32_t wOff = (uint32_t)((nHalf * 64 + (grp >> 1) * 8 + l8) * ROWW + (grp & 1) * 4) * 4;
    uint32_t wHiAddr = base + OFF_WHI * 4 + wOff;
    uint32_t wLoAddr = base + OFF_WLO * 4 + wOff;

    #pragma unroll
    for (int kc = 0; kc < 8; kc++) {
        uint32_t kB = kc * 32;
        uint32_t ah0, ah1, ah2, ah3, al0, al1, al2, al3;
        ldsm_x4(ah0, ah1, ah2, ah3, aHiAddr + kB);
        ldsm_x4(al0, al1, al2, al3, aLoAddr + kB);
        #pragma unroll
        for (int jp = 0; jp < 4; jp++) {
            uint32_t jB = (uint32_t)(jp * 16 * ROWW) * 4 + kB;
            uint32_t bh0, bh1, bh2, bh3, bl0, bl1, bl2, bl3;
            ldsm_x4(bh0, bh1, bh2, bh3, wHiAddr + jB);
            ldsm_x4(bl0, bl1, bl2, bl3, wLoAddr + jB);
            mma_bf16(acc[2 * jp],     ah0, ah1, ah2, ah3, bh0, bh1);
            mma_bf16(acc[2 * jp + 1], ah0, ah1, ah2, ah3, bh2, bh3);
            mma_bf16(acc[2 * jp],     al0, al1, al2, al3, bh0, bh1);
            mma_bf16(acc[2 * jp + 1], al0, al1, al2, al3, bh2, bh3);
            mma_bf16(acc[2 * jp],     ah0, ah1, ah2, ah3, bl0, bl1);
            mma_bf16(acc[2 * jp + 1], ah0, ah1, ah2, ah3, bl2, bl3);
        }
    }

    int gr0 = blockRow + rowGrp * 16 + g;
    int gr1 = gr0 + 8;
    float wn0 = (gr0 < NN) ? rsqrtf((float)(g_cnt[gr0] + 1)) : 0.f;
    float wn1 = (gr1 < NN) ? rsqrtf((float)(g_cnt[gr1] + 1)) : 0.f;
    #pragma unroll
    for (int j = 0; j < 8; j++) {
        int col = nHalf * 64 + j * 8 + 2 * t;
        if (gr0 < NN)
            *(__half2*)&outH[(size_t)gr0 * HID + col] =
                __floats2half2_rn(wn0 * acc[j][0], wn0 * acc[j][1]);
        if (gr1 < NN)
            *(__half2*)&outH[(size_t)gr1 * HID + col] =
                __floats2half2_rn(wn1 * acc[j][2], wn1 * acc[j][3]);
    }
}

// Split fp32 pair -> bf16 hi/lo words into A tiles
__device__ __forceinline__ void store_split(uint32_t* sAhi, uint32_t* sAlo,
                                            int row, int c, float v0, float v1) {
    __nv_bfloat16 h0 = __float2bfloat16(v0), h1 = __float2bfloat16(v1);
    __nv_bfloat16 l0 = __float2bfloat16(v0 - __bfloat162float(h0));
    __nv_bfloat16 l1 = __float2bfloat16(v1 - __bfloat162float(h1));
    sAhi[row * ROWW + c] = (uint32_t)__bfloat16_as_ushort(h0) | ((uint32_t)__bfloat16_as_ushort(h1) << 16);
    sAlo[row * ROWW + c] = (uint32_t)__bfloat16_as_ushort(l0) | ((uint32_t)__bfloat16_as_ushort(l1) << 16);
}

// ---------------- GEMM1: fp32 emb -> h1' (standalone) ------------------------
__global__ void __launch_bounds__(256, 2) k_gemm1(const float* __restrict__ Af32) {
    extern __shared__ uint32_t sm[];
    uint32_t* sAhi = sm;
    uint32_t* sAlo = sm + MAT_A;
    uint32_t* sWhi = sm + OFF_WHI;
    uint32_t* sWlo = sm + OFF_WLO;

    int tid = threadIdx.x;
    int blockRow = blockIdx.x * 64;

    #pragma unroll
    for (int i = 0; i < 32; i++) {
        int idx = tid + i * 256;
        int row = idx >> 6, c = idx & 63;
        sWhi[row * ROWW + c] = g_W1hi[idx];
        sWlo[row * ROWW + c] = g_W1lo[idx];
    }
    #pragma unroll
    for (int i = 0; i < 16; i++) {
        int idx = tid + i * 256;
        int row = idx >> 6, c = idx & 63;
        int gr = blockRow + row;
        float2 v = make_float2(0.f, 0.f);
        if (gr < NN) v = *(const float2*)&Af32[(size_t)gr * HID + 2 * c];
        store_split(sAhi, sAlo, row, c, v.x, v.y);
    }
    __syncthreads();
    gemm_core(sm, blockRow, g_bufH1, tid >> 5, tid & 31);
}

// ---------------- FUSED: agg(layer1) + GEMM2 ---------------------------------
// Phase 1: each warp aggregates 8 nodes from g_bufH1 (CSR gather), applies
// bias+relu, writes x split bf16 hi/lo straight into smem A tiles.
// Phase 2: GEMM with W2 -> g_bufH2.
__global__ void __launch_bounds__(256, 2) k_aggemm(const float* __restrict__ b1) {
    extern __shared__ uint32_t sm[];
    uint32_t* sAhi = sm;
    uint32_t* sAlo = sm + MAT_A;
    uint32_t* sWhi = sm + OFF_WHI;
    uint32_t* sWlo = sm + OFF_WLO;

    int tid = threadIdx.x;
    int wid = tid >> 5, lane = tid & 31;
    int blockRow = blockIdx.x * 64;
    const __half* h = g_bufH1;

    // Stage W2 images
    #pragma unroll
    for (int i = 0; i < 32; i++) {
        int idx = tid + i * 256;
        int row = idx >> 6, c = idx & 63;
        sWhi[row * ROWW + c] = g_W2hi[idx];
        sWlo[row * ROWW + c] = g_W2lo[idx];
    }

    // Phase 1: aggregate 8 nodes per warp
    float2 bv0 = *(const float2*)&b1[lane * 4];
    float2 bv1 = *(const float2*)&b1[lane * 4 + 2];
    #pragma unroll
    for (int i = 0; i < 8; i++) {
        int row = wid * 8 + i;
        int n = blockRow + row;
        float ax = 0.f, ay = 0.f, az = 0.f, aw = 0.f;
        int cnt = 0;
        if (n < NN) {
            uint2 v = ((const uint2*)(h + (size_t)n * HID))[lane];
            float2 p0 = __half22float2(*(const __half2*)&v.x);
            float2 p1 = __half22float2(*(const __half2*)&v.y);
            ax = p0.x; ay = p0.y; az = p1.x; aw = p1.y;   // self term

            int beg = g_rowptr[n];
            cnt = g_cnt[n];
            int end = beg + cnt;
            int idx = beg;
            for (; idx + 3 < end; idx += 4) {
                int s0 = g_col[idx];
                int s1 = g_col[idx + 1];
                int s2 = g_col[idx + 2];
                int s3 = g_col[idx + 3];
                uint2 v0 = ((const uint2*)(h + (size_t)s0 * HID))[lane];
                uint2 v1 = ((const uint2*)(h + (size_t)s1 * HID))[lane];
                uint2 v2 = ((const uint2*)(h + (size_t)s2 * HID))[lane];
                uint2 v3 = ((const uint2*)(h + (size_t)s3 * HID))[lane];
                float2 a0 = __half22float2(*(const __half2*)&v0.x);
                float2 c0 = __half22float2(*(const __half2*)&v0.y);
                float2 a1 = __half22float2(*(const __half2*)&v1.x);
                float2 c1 = __half22float2(*(const __half2*)&v1.y);
                float2 a2 = __half22float2(*(const __half2*)&v2.x);
                float2 c2 = __half22float2(*(const __half2*)&v2.y);
                float2 a3 = __half22float2(*(const __half2*)&v3.x);
                float2 c3 = __half22float2(*(const __half2*)&v3.y);
                ax += (a0.x + a1.x) + (a2.x + a3.x);
                ay += (a0.y + a1.y) + (a2.y + a3.y);
                az += (c0.x + c1.x) + (c2.x + c3.x);
                aw += (c0.y + c1.y) + (c2.y + c3.y);
            }
            for (; idx < end; idx++) {
                int s0 = g_col[idx];
                uint2 v0 = ((const uint2*)(h + (size_t)s0 * HID))[lane];
                float2 a0 = __half22float2(*(const __half2*)&v0.x);
                float2 c0 = __half22float2(*(const __half2*)&v0.y);
                ax += a0.x; ay += a0.y; az += c0.x; aw += c0.y;
            }
        }
        float wn = rsqrtf((float)(cnt + 1));
        float rx = fmaxf(wn * ax + bv0.x, 0.f);
        float ry = fmaxf(wn * ay + bv0.y, 0.f);
        float rz = fmaxf(wn * az + bv1.x, 0.f);
        float rw = fmaxf(wn * aw + bv1.y, 0.f);
        // write x split into A tiles (lane owns word cols 2*lane, 2*lane+1)
        store_split(sAhi, sAlo, row, 2 * lane,     rx, ry);
        store_split(sAhi, sAlo, row, 2 * lane + 1, rz, rw);
    }
    __syncthreads();

    // Phase 2: GEMM with W2
    gemm_core(sm, blockRow, g_bufH2, wid, lane);
}

// ---------------- final agg (layer 2) + fused output projection --------------
__global__ void k_agg2(const float* __restrict__ bias,
                       const float* __restrict__ Wout, const float* __restrict__ bout,
                       float* __restrict__ out) {
    const __half* h = g_bufH2;
    __shared__ float Ws[HID * NC];
    __shared__ float bs[NC];

    int tid = threadIdx.x;
    for (int i = tid; i < HID * NC; i += blockDim.x) Ws[i] = Wout[i];
    if (tid < NC) bs[tid] = bout[tid];
    __syncthreads();

    int n = (blockIdx.x * blockDim.x + tid) >> 5;     // grid exact: 100000 warps
    int lane = tid & 31;

    float ax, ay, az, aw;
    {
        uint2 v = ((const uint2*)(h + (size_t)n * HID))[lane];
        float2 p0 = __half22float2(*(const __half2*)&v.x);
        float2 p1 = __half22float2(*(const __half2*)&v.y);
        ax = p0.x; ay = p0.y; az = p1.x; aw = p1.y;
    }

    int beg = g_rowptr[n];
    int cnt = g_cnt[n];
    int end = beg + cnt;

    int idx = beg;
    for (; idx + 3 < end; idx += 4) {
        int s0 = g_col[idx];
        int s1 = g_col[idx + 1];
        int s2 = g_col[idx + 2];
        int s3 = g_col[idx + 3];
        uint2 v0 = ((const uint2*)(h + (size_t)s0 * HID))[lane];
        uint2 v1 = ((const uint2*)(h + (size_t)s1 * HID))[lane];
        uint2 v2 = ((const uint2*)(h + (size_t)s2 * HID))[lane];
        uint2 v3 = ((const uint2*)(h + (size_t)s3 * HID))[lane];
        float2 a0 = __half22float2(*(const __half2*)&v0.x);
        float2 b0 = __half22float2(*(const __half2*)&v0.y);
        float2 a1 = __half22float2(*(const __half2*)&v1.x);
        float2 b1 = __half22float2(*(const __half2*)&v1.y);
        float2 a2 = __half22float2(*(const __half2*)&v2.x);
        float2 b2 = __half22float2(*(const __half2*)&v2.y);
        float2 a3 = __half22float2(*(const __half2*)&v3.x);
        float2 b3 = __half22float2(*(const __half2*)&v3.y);
        ax += (a0.x + a1.x) + (a2.x + a3.x);
        ay += (a0.y + a1.y) + (a2.y + a3.y);
        az += (b0.x + b1.x) + (b2.x + b3.x);
        aw += (b0.y + b1.y) + (b2.y + b3.y);
    }
    for (; idx < end; idx++) {
        int s0 = g_col[idx];
        uint2 v0 = ((const uint2*)(h + (size_t)s0 * HID))[lane];
        float2 a0 = __half22float2(*(const __half2*)&v0.x);
        float2 b0 = __half22float2(*(const __half2*)&v0.y);
        ax += a0.x; ay += a0.y; az += b0.x; aw += b0.y;
    }

    float wn = rsqrtf((float)(cnt + 1));
    float4 bv = ((const float4*)bias)[lane];
    float rx = fmaxf(wn * ax + bv.x, 0.f);
    float ry = fmaxf(wn * ay + bv.y, 0.f);
    float rz = fmaxf(wn * az + bv.z, 0.f);
    float rw = fmaxf(wn * aw + bv.w, 0.f);

    int kb = lane * 4;
    #pragma unroll
    for (int c = 0; c < NC; c++) {
        float s = rx * Ws[(kb + 0) * NC + c]
                + ry * Ws[(kb + 1) * NC + c]
                + rz * Ws[(kb + 2) * NC + c]
                + rw * Ws[(kb + 3) * NC + c];
        #pragma unroll
        for (int off = 16; off; off >>= 1)
            s += __shfl_down_sync(0xffffffffu, s, off);
        if (lane == 0) out[(size_t)n * NC + c] = s + bs[c];
    }
}

// ---------------- launch ----------------
extern "C" void kernel_launch(void* const* d_in, const int* in_sizes, int n_in,
                              void* d_out, int out_size) {
    const int*   src  = (const int*)d_in[0];          // edge_index[0]
    const int*   dst  = src + NE;                     // edge_index[1]
    const float* emb  = (const float*)d_in[1];
    const float* W1   = (const float*)d_in[2];
    const float* b1   = (const float*)d_in[3];
    const float* W2   = (const float*)d_in[4];
    const float* b2   = (const float*)d_in[5];
    const float* Wout = (const float*)d_in[6];
    const float* bout = (const float*)d_in[7];
    float* out = (float*)d_out;

    const int SCAN_BLKS  = (NN + 511) / 512;          // 196
    const int EDGE4_BLKS = (NE / 4 + 255) / 256;      // 1563
    const int GEMM_BLKS  = (NN + 63) / 64;            // 1563
    const int AGG_BLKS   = (NN * 32) / 256;           // 12500

    static cudaStream_t s2 = nullptr;
    static cudaEvent_t evF = nullptr, evI = nullptr, evJ = nullptr;
    static void* cntAddr = nullptr;
    if (!s2) {
        cudaFuncSetAttribute(k_gemm1, cudaFuncAttributeMaxDynamicSharedMemorySize, DSMEM_SZ);
        cudaFuncSetAttribute(k_aggemm, cudaFuncAttributeMaxDynamicSharedMemorySize, DSMEM_SZ);
        cudaStreamCreateWithFlags(&s2, cudaStreamNonBlocking);
        cudaEventCreateWithFlags(&evF, cudaEventDisableTiming);
        cudaEventCreateWithFlags(&evI, cudaEventDisableTiming);
        cudaEventCreateWithFlags(&evJ, cudaEventDisableTiming);
        cudaGetSymbolAddress(&cntAddr, g_cnt);
    }

    // Fork: side stream starts weight images immediately (input-only deps)
    cudaEventRecord(evF, 0);
    cudaStreamWaitEvent(s2, evF, 0);
    k_wimg<<<32, 256, 0, s2>>>(W1, 0);
    k_wimg<<<32, 256, 0, s2>>>(W2, 1);

    // Main stream: counts (GEMM1's only prep dependency — epilogue rsqrt inline)
    cudaMemsetAsync(cntAddr, 0, NN * sizeof(int), 0);
    k_count<<<EDGE4_BLKS, 256>>>(dst);
    cudaEventRecord(evI, 0);

    // Side stream: GEMM1 overlaps remaining CSR build
    cudaStreamWaitEvent(s2, evI, 0);
    k_gemm1<<<GEMM_BLKS, 256, DSMEM_SZ, s2>>>(emb);
    cudaEventRecord(evJ, s2);

    // Main stream: rest of CSR build
    k_scanA<<<SCAN_BLKS, 512>>>();
    k_scanB<<<1, 256>>>(SCAN_BLKS);
    k_scanC<<<SCAN_BLKS, 512>>>();
    k_place<<<EDGE4_BLKS, 256>>>(src, dst);

    // Join; fused agg1+GEMM2; final agg2 + output projection
    cudaStreamWaitEvent(0, evJ, 0);
    k_aggemm<<<GEMM_BLKS, 256, DSMEM_SZ>>>(b1);
    k_agg2<<<AGG_BLKS, 256>>>(b2, Wout, bout, out);
}

// round 13
// speedup vs baseline: 1.1772x; 1.1772x over previous
#include <cuda_runtime.h>
#include <cuda_fp16.h>
#include <math.h>
#include <cstdint>

#define NN 100000
#define HID 128
#define NE 1600000
#define NC 10

// ---------------- scratch (device globals; no allocation allowed) -------------
__device__ int    g_cnt[NN];
__device__ int    g_rowptr[NN];
__device__ int    g_col[NE];
__device__ int    g_pos[NE];                   // intra-segment position per edge
__device__ int    g_blockSums[256];
__device__ __half g_bufH1[(size_t)NN * HID];   // layer-1 h' = invs*h (fp16)
__device__ __half g_bufH2[(size_t)NN * HID];   // layer-2 h' (fp16)
__device__ __half g_bufX[(size_t)NN * HID];    // layer-1 activation x (fp16)
// fp16 hi/lo weight images, layout [n][k/2] u32 pairs
__device__ uint32_t g_W1hi[128 * 64];
__device__ uint32_t g_W1lo[128 * 64];
__device__ uint32_t g_W2hi[128 * 64];
__device__ uint32_t g_W2lo[128 * 64];

__device__ __forceinline__ uint32_t smem_u32(const void* p) {
    uint32_t a;
    asm("{ .reg .u64 t; cvta.to.shared.u64 t, %1; cvt.u32.u64 %0, t; }" : "=r"(a) : "l"(p));
    return a;
}

// ---------------- degree histogram + position record (single atomic pass) ----
__global__ void k_count(const int* __restrict__ dst) {
    int e4 = blockIdx.x * blockDim.x + threadIdx.x;
    if (e4 < NE / 4) {
        int4 d = ((const int4*)dst)[e4];
        int4 p;
        p.x = atomicAdd(&g_cnt[d.x], 1);
        p.y = atomicAdd(&g_cnt[d.y], 1);
        p.z = atomicAdd(&g_cnt[d.z], 1);
        p.w = atomicAdd(&g_cnt[d.w], 1);
        ((int4*)g_pos)[e4] = p;
    }
}

// ---------------- exclusive scan (3-phase) ----------------
__global__ void k_scanA() {
    __shared__ int s[512];
    int i = blockIdx.x * 512 + threadIdx.x;
    int v = (i < NN) ? g_cnt[i] : 0;
    s[threadIdx.x] = v;
    __syncthreads();
    #pragma unroll
    for (int off = 1; off < 512; off <<= 1) {
        int t = (threadIdx.x >= off) ? s[threadIdx.x - off] : 0;
        __syncthreads();
        s[threadIdx.x] += t;
        __syncthreads();
    }
    if (i < NN) g_rowptr[i] = s[threadIdx.x] - v;        // exclusive
    if (threadIdx.x == 511) g_blockSums[blockIdx.x] = s[511];
}

__global__ void k_scanB(int nblocks) {
    __shared__ int s[256];
    int t = threadIdx.x;
    int v = (t < nblocks) ? g_blockSums[t] : 0;
    s[t] = v;
    __syncthreads();
    #pragma unroll
    for (int off = 1; off < 256; off <<= 1) {
        int u = (t >= off) ? s[t - off] : 0;
        __syncthreads();
        s[t] += u;
        __syncthreads();
    }
    if (t < nblocks) g_blockSums[t] = s[t] - v;           // exclusive
}

__global__ void k_scanC() {
    int i = blockIdx.x * 512 + threadIdx.x;
    if (i < NN) g_rowptr[i] += g_blockSums[blockIdx.x];
}

// ---------------- CSR place (no atomics) ----------------
__global__ void k_place(const int* __restrict__ src, const int* __restrict__ dst) {
    int e4 = blockIdx.x * blockDim.x + threadIdx.x;
    if (e4 < NE / 4) {
        int4 s = ((const int4*)src)[e4];
        int4 d = ((const int4*)dst)[e4];
        int4 p = ((const int4*)g_pos)[e4];
        g_col[g_rowptr[d.x] + p.x] = s.x;
        g_col[g_rowptr[d.y] + p.y] = s.y;
        g_col[g_rowptr[d.z] + p.z] = s.z;
        g_col[g_rowptr[d.w] + p.w] = s.w;
    }
}

// ---------------- weight image precompute (fp16 hi/lo) ----------------
__global__ void k_wimg(const float* __restrict__ W, int layer) {
    uint32_t* hiImg = (layer == 0 ? g_W1hi : g_W2hi);
    uint32_t* loImg = (layer == 0 ? g_W1lo : g_W2lo);
    int idx = blockIdx.x * blockDim.x + threadIdx.x;      // 0..8191 (pairs)
    if (idx >= 128 * 64) return;
    int n = idx >> 6, cp = idx & 63;
    int k0 = 2 * cp;
    float w0 = W[(size_t)k0 * HID + n];
    float w1 = W[(size_t)(k0 + 1) * HID + n];
    __half h0 = __float2half_rn(w0), h1 = __float2half_rn(w1);
    __half l0 = __float2half_rn(w0 - __half2float(h0));
    __half l1 = __float2half_rn(w1 - __half2float(h1));
    hiImg[idx] = (uint32_t)__half_as_ushort(h0) | ((uint32_t)__half_as_ushort(h1) << 16);
    loImg[idx] = (uint32_t)__half_as_ushort(l0) | ((uint32_t)__half_as_ushort(l1) << 16);
}

// ---------------- shared GEMM pieces -----------------------------------------
#define ROWW 68
#define MAT_A (64 * ROWW)                  // 4352 words (one 64-row A tile)
#define MAT_W (128 * ROWW)                 // 8704 words (one W image)
// GEMM1 smem: Ahi, Alo, Whi, Wlo
#define G1_WHI (2 * MAT_A)
#define G1_WLO (G1_WHI + MAT_W)
#define DSMEM1 ((G1_WLO + MAT_W) * 4)      // 104448 bytes
// GEMM2 smem: A (exact fp16), Whi, Wlo
#define G2_WHI (MAT_A)
#define G2_WLO (G2_WHI + MAT_W)
#define DSMEM2 ((G2_WLO + MAT_W) * 4)      // 87040 bytes

__device__ __forceinline__ void mma_f16(float* d, uint32_t a0, uint32_t a1,
                                        uint32_t a2, uint32_t a3,
                                        uint32_t b0, uint32_t b1) {
    asm volatile(
        "mma.sync.aligned.m16n8k16.row.col.f32.f16.f16.f32 "
        "{%0,%1,%2,%3}, {%4,%5,%6,%7}, {%8,%9}, {%0,%1,%2,%3};\n"
        : "+f"(d[0]), "+f"(d[1]), "+f"(d[2]), "+f"(d[3])
        : "r"(a0), "r"(a1), "r"(a2), "r"(a3), "r"(b0), "r"(b1));
}

__device__ __forceinline__ void ldsm_x4(uint32_t& r0, uint32_t& r1, uint32_t& r2,
                                        uint32_t& r3, uint32_t addr) {
    asm volatile("ldmatrix.sync.aligned.m8n8.x4.shared.b16 {%0,%1,%2,%3}, [%4];"
                 : "=r"(r0), "=r"(r1), "=r"(r2), "=r"(r3) : "r"(addr));
}

// Epilogue: scale by rsqrt(cnt+1), store fp16 h'
__device__ __forceinline__ void gemm_epilogue(float acc[8][4], int blockRow,
                                              __half* outH, int wid, int lane) {
    int g = lane >> 2, t = lane & 3;
    int rowGrp = wid & 3, nHalf = wid >> 2;
    int gr0 = blockRow + rowGrp * 16 + g;
    int gr1 = gr0 + 8;
    float wn0 = (gr0 < NN) ? rsqrtf((float)(g_cnt[gr0] + 1)) : 0.f;
    float wn1 = (gr1 < NN) ? rsqrtf((float)(g_cnt[gr1] + 1)) : 0.f;
    #pragma unroll
    for (int j = 0; j < 8; j++) {
        int col = nHalf * 64 + j * 8 + 2 * t;
        if (gr0 < NN)
            *(__half2*)&outH[(size_t)gr0 * HID + col] =
                __floats2half2_rn(wn0 * acc[j][0], wn0 * acc[j][1]);
        if (gr1 < NN)
            *(__half2*)&outH[(size_t)gr1 * HID + col] =
                __floats2half2_rn(wn1 * acc[j][2], wn1 * acc[j][3]);
    }
}

// ---------------- GEMM1: fp32 emb, 3-pass fp16 split -> g_bufH1 --------------
__global__ void __launch_bounds__(256, 2) k_gemm1(const float* __restrict__ Af32) {
    extern __shared__ uint32_t sm[];
    uint32_t* sAhi = sm;
    uint32_t* sAlo = sm + MAT_A;
    uint32_t* sWhi = sm + G1_WHI;
    uint32_t* sWlo = sm + G1_WLO;

    int tid = threadIdx.x;
    int wid = tid >> 5, lane = tid & 31;
    int blockRow = blockIdx.x * 64;

    #pragma unroll
    for (int i = 0; i < 32; i++) {
        int idx = tid + i * 256;
        int row = idx >> 6, c = idx & 63;
        sWhi[row * ROWW + c] = g_W1hi[idx];
        sWlo[row * ROWW + c] = g_W1lo[idx];
    }
    #pragma unroll
    for (int i = 0; i < 16; i++) {
        int idx = tid + i * 256;
        int row = idx >> 6, c = idx & 63;
        int gr = blockRow + row;
        float2 v = make_float2(0.f, 0.f);
        if (gr < NN) v = *(const float2*)&Af32[(size_t)gr * HID + 2 * c];
        __half h0 = __float2half_rn(v.x), h1 = __float2half_rn(v.y);
        __half l0 = __float2half_rn(v.x - __half2float(h0));
        __half l1 = __float2half_rn(v.y - __half2float(h1));
        sAhi[row * ROWW + c] = (uint32_t)__half_as_ushort(h0) | ((uint32_t)__half_as_ushort(h1) << 16);
        sAlo[row * ROWW + c] = (uint32_t)__half_as_ushort(l0) | ((uint32_t)__half_as_ushort(l1) << 16);
    }
    __syncthreads();

    float acc[8][4];
    #pragma unroll
    for (int j = 0; j < 8; j++)
        #pragma unroll
        for (int q = 0; q < 4; q++) acc[j][q] = 0.f;

    int rowGrp = wid & 3, nHalf = wid >> 2;
    int grp = lane >> 3, l8 = lane & 7;
    uint32_t base = smem_u32(sm);
    uint32_t aOff = (uint32_t)((rowGrp * 16 + (grp & 1) * 8 + l8) * ROWW + (grp >> 1) * 4) * 4;
    uint32_t aHiAddr = base + aOff;
    uint32_t aLoAddr = base + MAT_A * 4 + aOff;
    uint32_t wOff = (uint32_t)((nHalf * 64 + (grp >> 1) * 8 + l8) * ROWW + (grp & 1) * 4) * 4;
    uint32_t wHiAddr = base + G1_WHI * 4 + wOff;
    uint32_t wLoAddr = base + G1_WLO * 4 + wOff;

    #pragma unroll
    for (int kc = 0; kc < 8; kc++) {
        uint32_t kB = kc * 32;
        uint32_t ah0, ah1, ah2, ah3, al0, al1, al2, al3;
        ldsm_x4(ah0, ah1, ah2, ah3, aHiAddr + kB);
        ldsm_x4(al0, al1, al2, al3, aLoAddr + kB);
        #pragma unroll
        for (int jp = 0; jp < 4; jp++) {
            uint32_t jB = (uint32_t)(jp * 16 * ROWW) * 4 + kB;
            uint32_t bh0, bh1, bh2, bh3, bl0, bl1, bl2, bl3;
            ldsm_x4(bh0, bh1, bh2, bh3, wHiAddr + jB);
            ldsm_x4(bl0, bl1, bl2, bl3, wLoAddr + jB);
            mma_f16(acc[2 * jp],     ah0, ah1, ah2, ah3, bh0, bh1);
            mma_f16(acc[2 * jp + 1], ah0, ah1, ah2, ah3, bh2, bh3);
            mma_f16(acc[2 * jp],     al0, al1, al2, al3, bh0, bh1);
            mma_f16(acc[2 * jp + 1], al0, al1, al2, al3, bh2, bh3);
            mma_f16(acc[2 * jp],     ah0, ah1, ah2, ah3, bl0, bl1);
            mma_f16(acc[2 * jp + 1], ah0, ah1, ah2, ah3, bl2, bl3);
        }
    }
    gemm_epilogue(acc, blockRow, g_bufH1, wid, lane);
}

// ---------------- GEMM2: fp16 x (exact), 2-pass -> g_bufH2 -------------------
__global__ void __launch_bounds__(256, 2) k_gemm2() {
    extern __shared__ uint32_t sm[];
    uint32_t* sA = sm;
    uint32_t* sWhi = sm + G2_WHI;
    uint32_t* sWlo = sm + G2_WLO;

    int tid = threadIdx.x;
    int wid = tid >> 5, lane = tid & 31;
    int blockRow = blockIdx.x * 64;

    #pragma unroll
    for (int i = 0; i < 32; i++) {
        int idx = tid + i * 256;
        int row = idx >> 6, c = idx & 63;
        sWhi[row * ROWW + c] = g_W2hi[idx];
        sWlo[row * ROWW + c] = g_W2lo[idx];
    }
    // A tile: raw fp16 copy (exact — no conversion)
    #pragma unroll
    for (int i = 0; i < 16; i++) {
        int idx = tid + i * 256;
        int row = idx >> 6, c = idx & 63;
        int gr = blockRow + row;
        uint32_t u = 0;
        if (gr < NN) u = ((const uint32_t*)(g_bufX + (size_t)gr * HID))[c];
        sA[row * ROWW + c] = u;
    }
    __syncthreads();

    float acc[8][4];
    #pragma unroll
    for (int j = 0; j < 8; j++)
        #pragma unroll
        for (int q = 0; q < 4; q++) acc[j][q] = 0.f;

    int rowGrp = wid & 3, nHalf = wid >> 2;
    int grp = lane >> 3, l8 = lane & 7;
    uint32_t base = smem_u32(sm);
    uint32_t aOff = (uint32_t)((rowGrp * 16 + (grp & 1) * 8 + l8) * ROWW + (grp >> 1) * 4) * 4;
    uint32_t aAddr = base + aOff;
    uint32_t wOff = (uint32_t)((nHalf * 64 + (grp >> 1) * 8 + l8) * ROWW + (grp & 1) * 4) * 4;
    uint32_t wHiAddr = base + G2_WHI * 4 + wOff;
    uint32_t wLoAddr = base + G2_WLO * 4 + wOff;

    #pragma unroll
    for (int kc = 0; kc < 8; kc++) {
        uint32_t kB = kc * 32;
        uint32_t a0, a1, a2, a3;
        ldsm_x4(a0, a1, a2, a3, aAddr + kB);
        #pragma unroll
        for (int jp = 0; jp < 4; jp++) {
            uint32_t jB = (uint32_t)(jp * 16 * ROWW) * 4 + kB;
            uint32_t bh0, bh1, bh2, bh3, bl0, bl1, bl2, bl3;
            ldsm_x4(bh0, bh1, bh2, bh3, wHiAddr + jB);
            ldsm_x4(bl0, bl1, bl2, bl3, wLoAddr + jB);
            mma_f16(acc[2 * jp],     a0, a1, a2, a3, bh0, bh1);
            mma_f16(acc[2 * jp + 1], a0, a1, a2, a3, bh2, bh3);
            mma_f16(acc[2 * jp],     a0, a1, a2, a3, bl0, bl1);
            mma_f16(acc[2 * jp + 1], a0, a1, a2, a3, bl2, bl3);
        }
    }
    gemm_epilogue(acc, blockRow, g_bufH2, wid, lane);
}

// ---------------- gather-aggregate + bias + relu (+ fused output proj) -------
// agg[n] = rsqrt(cnt[n]+1) * sum_{s in N(n) U {n}} h'[s];  x = relu(agg + b)
__global__ void k_agg(int layer, const float* __restrict__ bias,
                      const float* __restrict__ Wout, const float* __restrict__ bout,
                      float* __restrict__ out) {
    const __half* h = (layer == 0 ? g_bufH1 : g_bufH2);
    __shared__ float Ws[HID * NC];
    __shared__ float bs[NC];

    int tid = threadIdx.x;
    if (Wout) {
        for (int i = tid; i < HID * NC; i += blockDim.x) Ws[i] = Wout[i];
        if (tid < NC) bs[tid] = bout[tid];
        __syncthreads();
    }

    int n = (blockIdx.x * blockDim.x + tid) >> 5;     // grid exact: 100000 warps
    int lane = tid & 31;

    float ax, ay, az, aw;
    {
        uint2 v = ((const uint2*)(h + (size_t)n * HID))[lane];
        float2 p0 = __half22float2(*(const __half2*)&v.x);
        float2 p1 = __half22float2(*(const __half2*)&v.y);
        ax = p0.x; ay = p0.y; az = p1.x; aw = p1.y;   // self term h'[n]
    }

    int beg = g_rowptr[n];
    int cnt = g_cnt[n];
    int end = beg + cnt;

    int idx = beg;
    for (; idx + 3 < end; idx += 4) {                 // 4-way MLP
        int s0 = g_col[idx];
        int s1 = g_col[idx + 1];
        int s2 = g_col[idx + 2];
        int s3 = g_col[idx + 3];
        uint2 v0 = ((const uint2*)(h + (size_t)s0 * HID))[lane];
        uint2 v1 = ((const uint2*)(h + (size_t)s1 * HID))[lane];
        uint2 v2 = ((const uint2*)(h + (size_t)s2 * HID))[lane];
        uint2 v3 = ((const uint2*)(h + (size_t)s3 * HID))[lane];
        float2 a0 = __half22float2(*(const __half2*)&v0.x);
        float2 b0 = __half22float2(*(const __half2*)&v0.y);
        float2 a1 = __half22float2(*(const __half2*)&v1.x);
        float2 b1 = __half22float2(*(const __half2*)&v1.y);
        float2 a2 = __half22float2(*(const __half2*)&v2.x);
        float2 b2 = __half22float2(*(const __half2*)&v2.y);
        float2 a3 = __half22float2(*(const __half2*)&v3.x);
        float2 b3 = __half22float2(*(const __half2*)&v3.y);
        ax += (a0.x + a1.x) + (a2.x + a3.x);
        ay += (a0.y + a1.y) + (a2.y + a3.y);
        az += (b0.x + b1.x) + (b2.x + b3.x);
        aw += (b0.y + b1.y) + (b2.y + b3.y);
    }
    for (; idx < end; idx++) {
        int s0 = g_col[idx];
        uint2 v0 = ((const uint2*)(h + (size_t)s0 * HID))[lane];
        float2 a0 = __half22float2(*(const __half2*)&v0.x);
        float2 b0 = __half22float2(*(const __half2*)&v0.y);
        ax += a0.x; ay += a0.y; az += b0.x; aw += b0.y;
    }

    float wn = rsqrtf((float)(cnt + 1));
    float4 bv = ((const float4*)bias)[lane];
    float4 r;
    r.x = fmaxf(wn * ax + bv.x, 0.f);
    r.y = fmaxf(wn * ay + bv.y, 0.f);
    r.z = fmaxf(wn * az + bv.z, 0.f);
    r.w = fmaxf(wn * aw + bv.w, 0.f);

    if (!Wout) {
        uint2 o;
        *(__half2*)&o.x = __floats2half2_rn(r.x, r.y);
        *(__half2*)&o.y = __floats2half2_rn(r.z, r.w);
        ((uint2*)(g_bufX + (size_t)n * HID))[lane] = o;
    } else {
        int kb = lane * 4;
        #pragma unroll
        for (int c = 0; c < NC; c++) {
            float s = r.x * Ws[(kb + 0) * NC + c]
                    + r.y * Ws[(kb + 1) * NC + c]
                    + r.z * Ws[(kb + 2) * NC + c]
                    + r.w * Ws[(kb + 3) * NC + c];
            #pragma unroll
            for (int off = 16; off; off >>= 1)
                s += __shfl_down_sync(0xffffffffu, s, off);
            if (lane == 0) out[(size_t)n * NC + c] = s + bs[c];
        }
    }
}

// ---------------- launch ----------------
extern "C" void kernel_launch(void* const* d_in, const int* in_sizes, int n_in,
                              void* d_out, int out_size) {
    const int*   src  = (const int*)d_in[0];          // edge_index[0]
    const int*   dst  = src + NE;                     // edge_index[1]
    const float* emb  = (const float*)d_in[1];
    const float* W1   = (const float*)d_in[2];
    const float* b1   = (const float*)d_in[3];
    const float* W2   = (const float*)d_in[4];
    const float* b2   = (const float*)d_in[5];
    const float* Wout = (const float*)d_in[6];
    const float* bout = (const float*)d_in[7];
    float* out = (float*)d_out;

    const int SCAN_BLKS  = (NN + 511) / 512;          // 196
    const int EDGE4_BLKS = (NE / 4 + 255) / 256;      // 1563
    const int GEMM_BLKS  = (NN + 63) / 64;            // 1563
    const int AGG_BLKS   = (NN * 32) / 256;           // 12500

    static cudaStream_t s2 = nullptr;
    static cudaEvent_t evF = nullptr, evI = nullptr, evJ = nullptr;
    static void* cntAddr = nullptr;
    if (!s2) {
        cudaFuncSetAttribute(k_gemm1, cudaFuncAttributeMaxDynamicSharedMemorySize, DSMEM1);
        cudaFuncSetAttribute(k_gemm2, cudaFuncAttributeMaxDynamicSharedMemorySize, DSMEM2);
        cudaStreamCreateWithFlags(&s2, cudaStreamNonBlocking);
        cudaEventCreateWithFlags(&evF, cudaEventDisableTiming);
        cudaEventCreateWithFlags(&evI, cudaEventDisableTiming);
        cudaEventCreateWithFlags(&evJ, cudaEventDisableTiming);
        cudaGetSymbolAddress(&cntAddr, g_cnt);
    }

    // Fork: side stream starts weight images immediately (input-only deps)
    cudaEventRecord(evF, 0);
    cudaStreamWaitEvent(s2, evF, 0);
    k_wimg<<<32, 256, 0, s2>>>(W1, 0);
    k_wimg<<<32, 256, 0, s2>>>(W2, 1);

    // Main stream: counts (GEMM1's only prep dependency — epilogue rsqrt inline)
    cudaMemsetAsync(cntAddr, 0, NN * sizeof(int), 0);
    k_count<<<EDGE4_BLKS, 256>>>(dst);
    cudaEventRecord(evI, 0);

    // Side stream: GEMM1 overlaps remaining CSR build
    cudaStreamWaitEvent(s2, evI, 0);
    k_gemm1<<<GEMM_BLKS, 256, DSMEM1, s2>>>(emb);
    cudaEventRecord(evJ, s2);

    // Main stream: rest of CSR build
    k_scanA<<<SCAN_BLKS, 512>>>();
    k_scanB<<<1, 256>>>(SCAN_BLKS);
    k_scanC<<<SCAN_BLKS, 512>>>();
    k_place<<<EDGE4_BLKS, 256>>>(src, dst);

    // Join, then layer-1 agg -> layer-2 GEMM -> layer-2 agg + output proj
    cudaStreamWaitEvent(0, evJ, 0);
    k_agg<<<AGG_BLKS, 256>>>(0, b1, nullptr, nullptr, nullptr);
    k_gemm2<<<GEMM_BLKS, 256, DSMEM2>>>();
    k_agg<<<AGG_BLKS, 256>>>(1, b2, Wout, bout, out);
}

// round 14
// speedup vs baseline: 1.2977x; 1.1023x over previous
#include <cuda_runtime.h>
#include <cuda_fp16.h>
#include <math.h>
#include <cstdint>

#define NN 100000
#define HID 128
#define NE 1600000
#define NC 10

// ---------------- scratch (device globals; no allocation allowed) -------------
__device__ int    g_cnt[NN];
__device__ int    g_rowptr[NN];
__device__ int    g_col[NE];
__device__ int    g_pos[NE];                   // intra-segment position per edge
__device__ int    g_blockSums[256];
__device__ __half g_bufH1[(size_t)NN * HID];   // layer-1 h' = invs*h (fp16)
__device__ __half g_bufH2[(size_t)NN * HID];   // layer-2 h' (fp16)
__device__ __half g_bufX[(size_t)NN * HID];    // layer-1 activation x (fp16)
// fp16 weight images, layout [n][k/2] u32 pairs (single precision level)
__device__ uint32_t g_W1i[128 * 64];
__device__ uint32_t g_W2i[128 * 64];

__device__ __forceinline__ uint32_t smem_u32(const void* p) {
    uint32_t a;
    asm("{ .reg .u64 t; cvta.to.shared.u64 t, %1; cvt.u32.u64 %0, t; }" : "=r"(a) : "l"(p));
    return a;
}

// ---------------- degree histogram + position record (single atomic pass) ----
__global__ void k_count(const int* __restrict__ dst) {
    int e4 = blockIdx.x * blockDim.x + threadIdx.x;
    if (e4 < NE / 4) {
        int4 d = ((const int4*)dst)[e4];
        int4 p;
        p.x = atomicAdd(&g_cnt[d.x], 1);
        p.y = atomicAdd(&g_cnt[d.y], 1);
        p.z = atomicAdd(&g_cnt[d.z], 1);
        p.w = atomicAdd(&g_cnt[d.w], 1);
        ((int4*)g_pos)[e4] = p;
    }
}

// ---------------- exclusive scan (3-phase) ----------------
__global__ void k_scanA() {
    __shared__ int s[512];
    int i = blockIdx.x * 512 + threadIdx.x;
    int v = (i < NN) ? g_cnt[i] : 0;
    s[threadIdx.x] = v;
    __syncthreads();
    #pragma unroll
    for (int off = 1; off < 512; off <<= 1) {
        int t = (threadIdx.x >= off) ? s[threadIdx.x - off] : 0;
        __syncthreads();
        s[threadIdx.x] += t;
        __syncthreads();
    }
    if (i < NN) g_rowptr[i] = s[threadIdx.x] - v;        // exclusive
    if (threadIdx.x == 511) g_blockSums[blockIdx.x] = s[511];
}

__global__ void k_scanB(int nblocks) {
    __shared__ int s[256];
    int t = threadIdx.x;
    int v = (t < nblocks) ? g_blockSums[t] : 0;
    s[t] = v;
    __syncthreads();
    #pragma unroll
    for (int off = 1; off < 256; off <<= 1) {
        int u = (t >= off) ? s[t - off] : 0;
        __syncthreads();
        s[t] += u;
        __syncthreads();
    }
    if (t < nblocks) g_blockSums[t] = s[t] - v;           // exclusive
}

__global__ void k_scanC() {
    int i = blockIdx.x * 512 + threadIdx.x;
    if (i < NN) g_rowptr[i] += g_blockSums[blockIdx.x];
}

// ---------------- CSR place (no atomics) ----------------
__global__ void k_place(const int* __restrict__ src, const int* __restrict__ dst) {
    int e4 = blockIdx.x * blockDim.x + threadIdx.x;
    if (e4 < NE / 4) {
        int4 s = ((const int4*)src)[e4];
        int4 d = ((const int4*)dst)[e4];
        int4 p = ((const int4*)g_pos)[e4];
        g_col[g_rowptr[d.x] + p.x] = s.x;
        g_col[g_rowptr[d.y] + p.y] = s.y;
        g_col[g_rowptr[d.z] + p.z] = s.z;
        g_col[g_rowptr[d.w] + p.w] = s.w;
    }
}

// ---------------- weight image precompute (single fp16) ----------------
__global__ void k_wimg(const float* __restrict__ W, int layer) {
    uint32_t* img = (layer == 0 ? g_W1i : g_W2i);
    int idx = blockIdx.x * blockDim.x + threadIdx.x;      // 0..8191 (pairs)
    if (idx >= 128 * 64) return;
    int n = idx >> 6, cp = idx & 63;
    int k0 = 2 * cp;
    float w0 = W[(size_t)k0 * HID + n];
    float w1 = W[(size_t)(k0 + 1) * HID + n];
    __half h0 = __float2half_rn(w0), h1 = __float2half_rn(w1);
    img[idx] = (uint32_t)__half_as_ushort(h0) | ((uint32_t)__half_as_ushort(h1) << 16);
}

// ---------------- single-pass fp16 GEMM, M-tile 64, 3 CTAs/SM ----------------
// h'[r][:] = rsqrt(cnt[r]+1) * (A[r][:] @ W), stored fp16.
#define ROWW 68
#define MAT_A (64 * ROWW)                  // 4352 words
#define MAT_W (128 * ROWW)                 // 8704 words
#define DSMEM_SZ ((MAT_A + MAT_W) * 4)     // 52224 bytes

__device__ __forceinline__ void mma_f16(float* d, uint32_t a0, uint32_t a1,
                                        uint32_t a2, uint32_t a3,
                                        uint32_t b0, uint32_t b1) {
    asm volatile(
        "mma.sync.aligned.m16n8k16.row.col.f32.f16.f16.f32 "
        "{%0,%1,%2,%3}, {%4,%5,%6,%7}, {%8,%9}, {%0,%1,%2,%3};\n"
        : "+f"(d[0]), "+f"(d[1]), "+f"(d[2]), "+f"(d[3])
        : "r"(a0), "r"(a1), "r"(a2), "r"(a3), "r"(b0), "r"(b1));
}

__device__ __forceinline__ void ldsm_x4(uint32_t& r0, uint32_t& r1, uint32_t& r2,
                                        uint32_t& r3, uint32_t addr) {
    asm volatile("ldmatrix.sync.aligned.m8n8.x4.shared.b16 {%0,%1,%2,%3}, [%4];"
                 : "=r"(r0), "=r"(r1), "=r"(r2), "=r"(r3) : "r"(addr));
}

__global__ void __launch_bounds__(256, 3) k_gemm(const float* Af32, int layer) {
    extern __shared__ uint32_t sm[];
    uint32_t* sA = sm;
    uint32_t* sW = sm + MAT_A;

    const uint32_t* wImg = (layer == 0 ? g_W1i : g_W2i);
    __half* outH = (layer == 0 ? g_bufH1 : g_bufH2);

    int tid = threadIdx.x;
    int wid = tid >> 5, lane = tid & 31;
    int blockRow = blockIdx.x * 64;

    // Stage W image
    #pragma unroll
    for (int i = 0; i < 32; i++) {
        int idx = tid + i * 256;
        int row = idx >> 6, c = idx & 63;
        sW[row * ROWW + c] = wImg[idx];
    }
    // A tile: layer 0 converts fp32 emb -> fp16; layer 1 raw-copies fp16 x
    #pragma unroll
    for (int i = 0; i < 16; i++) {
        int idx = tid + i * 256;
        int row = idx >> 6, c = idx & 63;
        int gr = blockRow + row;
        uint32_t u = 0;
        if (gr < NN) {
            if (Af32) {
                float2 v = *(const float2*)&Af32[(size_t)gr * HID + 2 * c];
                __half h0 = __float2half_rn(v.x), h1 = __float2half_rn(v.y);
                u = (uint32_t)__half_as_ushort(h0) | ((uint32_t)__half_as_ushort(h1) << 16);
            } else {
                u = ((const uint32_t*)(g_bufX + (size_t)gr * HID))[c];
            }
        }
        sA[row * ROWW + c] = u;
    }
    __syncthreads();

    float acc[8][4];
    #pragma unroll
    for (int j = 0; j < 8; j++)
        #pragma unroll
        for (int q = 0; q < 4; q++) acc[j][q] = 0.f;

    int rowGrp = wid & 3, nHalf = wid >> 2;
    int grp = lane >> 3, l8 = lane & 7;
    uint32_t base = smem_u32(sm);
    uint32_t aAddr = base + (uint32_t)((rowGrp * 16 + (grp & 1) * 8 + l8) * ROWW + (grp >> 1) * 4) * 4;
    uint32_t wAddr = base + MAT_A * 4 +
                     (uint32_t)((nHalf * 64 + (grp >> 1) * 8 + l8) * ROWW + (grp & 1) * 4) * 4;

    #pragma unroll
    for (int kc = 0; kc < 8; kc++) {
        uint32_t kB = kc * 32;
        uint32_t a0, a1, a2, a3;
        ldsm_x4(a0, a1, a2, a3, aAddr + kB);
        #pragma unroll
        for (int jp = 0; jp < 4; jp++) {
            uint32_t jB = (uint32_t)(jp * 16 * ROWW) * 4 + kB;
            uint32_t b0, b1, b2, b3;
            ldsm_x4(b0, b1, b2, b3, wAddr + jB);
            mma_f16(acc[2 * jp],     a0, a1, a2, a3, b0, b1);
            mma_f16(acc[2 * jp + 1], a0, a1, a2, a3, b2, b3);
        }
    }

    // Epilogue: scale by rsqrt(cnt+1), store fp16 h'
    int g = lane >> 2, t = lane & 3;
    int gr0 = blockRow + rowGrp * 16 + g;
    int gr1 = gr0 + 8;
    float wn0 = (gr0 < NN) ? rsqrtf((float)(g_cnt[gr0] + 1)) : 0.f;
    float wn1 = (gr1 < NN) ? rsqrtf((float)(g_cnt[gr1] + 1)) : 0.f;
    #pragma unroll
    for (int j = 0; j < 8; j++) {
        int col = nHalf * 64 + j * 8 + 2 * t;
        if (gr0 < NN)
            *(__half2*)&outH[(size_t)gr0 * HID + col] =
                __floats2half2_rn(wn0 * acc[j][0], wn0 * acc[j][1]);
        if (gr1 < NN)
            *(__half2*)&outH[(size_t)gr1 * HID + col] =
                __floats2half2_rn(wn1 * acc[j][2], wn1 * acc[j][3]);
    }
}

// ---------------- gather-aggregate + bias + relu (+ fused output proj) -------
// agg[n] = rsqrt(cnt[n]+1) * sum_{s in N(n) U {n}} h'[s];  x = relu(agg + b)
__global__ void k_agg(int layer, const float* __restrict__ bias,
                      const float* __restrict__ Wout, const float* __restrict__ bout,
                      float* __restrict__ out) {
    const __half* h = (layer == 0 ? g_bufH1 : g_bufH2);
    __shared__ float Ws[HID * NC];
    __shared__ float bs[NC];

    int tid = threadIdx.x;
    if (Wout) {
        for (int i = tid; i < HID * NC; i += blockDim.x) Ws[i] = Wout[i];
        if (tid < NC) bs[tid] = bout[tid];
        __syncthreads();
    }

    int n = (blockIdx.x * blockDim.x + tid) >> 5;     // grid exact: 100000 warps
    int lane = tid & 31;

    float ax, ay, az, aw;
    {
        uint2 v = ((const uint2*)(h + (size_t)n * HID))[lane];
        float2 p0 = __half22float2(*(const __half2*)&v.x);
        float2 p1 = __half22float2(*(const __half2*)&v.y);
        ax = p0.x; ay = p0.y; az = p1.x; aw = p1.y;   // self term h'[n]
    }

    int beg = g_rowptr[n];
    int cnt = g_cnt[n];
    int end = beg + cnt;

    int idx = beg;
    for (; idx + 3 < end; idx += 4) {                 // 4-way MLP
        int s0 = g_col[idx];
        int s1 = g_col[idx + 1];
        int s2 = g_col[idx + 2];
        int s3 = g_col[idx + 3];
        uint2 v0 = ((const uint2*)(h + (size_t)s0 * HID))[lane];
        uint2 v1 = ((const uint2*)(h + (size_t)s1 * HID))[lane];
        uint2 v2 = ((const uint2*)(h + (size_t)s2 * HID))[lane];
        uint2 v3 = ((const uint2*)(h + (size_t)s3 * HID))[lane];
        float2 a0 = __half22float2(*(const __half2*)&v0.x);
        float2 b0 = __half22float2(*(const __half2*)&v0.y);
        float2 a1 = __half22float2(*(const __half2*)&v1.x);
        float2 b1 = __half22float2(*(const __half2*)&v1.y);
        float2 a2 = __half22float2(*(const __half2*)&v2.x);
        float2 b2 = __half22float2(*(const __half2*)&v2.y);
        float2 a3 = __half22float2(*(const __half2*)&v3.x);
        float2 b3 = __half22float2(*(const __half2*)&v3.y);
        ax += (a0.x + a1.x) + (a2.x + a3.x);
        ay += (a0.y + a1.y) + (a2.y + a3.y);
        az += (b0.x + b1.x) + (b2.x + b3.x);
        aw += (b0.y + b1.y) + (b2.y + b3.y);
    }
    for (; idx < end; idx++) {
        int s0 = g_col[idx];
        uint2 v0 = ((const uint2*)(h + (size_t)s0 * HID))[lane];
        float2 a0 = __half22float2(*(const __half2*)&v0.x);
        float2 b0 = __half22float2(*(const __half2*)&v0.y);
        ax += a0.x; ay += a0.y; az += b0.x; aw += b0.y;
    }

    float wn = rsqrtf((float)(cnt + 1));
    float4 bv = ((const float4*)bias)[lane];
    float4 r;
    r.x = fmaxf(wn * ax + bv.x, 0.f);
    r.y = fmaxf(wn * ay + bv.y, 0.f);
    r.z = fmaxf(wn * az + bv.z, 0.f);
    r.w = fmaxf(wn * aw + bv.w, 0.f);

    if (!Wout) {
        uint2 o;
        *(__half2*)&o.x = __floats2half2_rn(r.x, r.y);
        *(__half2*)&o.y = __floats2half2_rn(r.z, r.w);
        ((uint2*)(g_bufX + (size_t)n * HID))[lane] = o;
    } else {
        int kb = lane * 4;
        #pragma unroll
        for (int c = 0; c < NC; c++) {
            float s = r.x * Ws[(kb + 0) * NC + c]
                    + r.y * Ws[(kb + 1) * NC + c]
                    + r.z * Ws[(kb + 2) * NC + c]
                    + r.w * Ws[(kb + 3) * NC + c];
            #pragma unroll
            for (int off = 16; off; off >>= 1)
                s += __shfl_down_sync(0xffffffffu, s, off);
            if (lane == 0) out[(size_t)n * NC + c] = s + bs[c];
        }
    }
}

// ---------------- launch ----------------
extern "C" void kernel_launch(void* const* d_in, const int* in_sizes, int n_in,
                              void* d_out, int out_size) {
    const int*   src  = (const int*)d_in[0];          // edge_index[0]
    const int*   dst  = src + NE;                     // edge_index[1]
    const float* emb  = (const float*)d_in[1];
    const float* W1   = (const float*)d_in[2];
    const float* b1   = (const float*)d_in[3];
    const float* W2   = (const float*)d_in[4];
    const float* b2   = (const float*)d_in[5];
    const float* Wout = (const float*)d_in[6];
    const float* bout = (const float*)d_in[7];
    float* out = (float*)d_out;

    const int SCAN_BLKS  = (NN + 511) / 512;          // 196
    const int EDGE4_BLKS = (NE / 4 + 255) / 256;      // 1563
    const int GEMM_BLKS  = (NN + 63) / 64;            // 1563
    const int AGG_BLKS   = (NN * 32) / 256;           // 12500

    static cudaStream_t s2 = nullptr;
    static cudaEvent_t evF = nullptr, evI = nullptr, evJ = nullptr;
    static void* cntAddr = nullptr;
    if (!s2) {
        cudaFuncSetAttribute(k_gemm, cudaFuncAttributeMaxDynamicSharedMemorySize, DSMEM_SZ);
        cudaStreamCreateWithFlags(&s2, cudaStreamNonBlocking);
        cudaEventCreateWithFlags(&evF, cudaEventDisableTiming);
        cudaEventCreateWithFlags(&evI, cudaEventDisableTiming);
        cudaEventCreateWithFlags(&evJ, cudaEventDisableTiming);
        cudaGetSymbolAddress(&cntAddr, g_cnt);
    }

    // Fork: side stream starts weight images immediately (input-only deps)
    cudaEventRecord(evF, 0);
    cudaStreamWaitEvent(s2, evF, 0);
    k_wimg<<<32, 256, 0, s2>>>(W1, 0);
    k_wimg<<<32, 256, 0, s2>>>(W2, 1);

    // Main stream: counts (GEMM1's only prep dependency — epilogue rsqrt inline)
    cudaMemsetAsync(cntAddr, 0, NN * sizeof(int), 0);
    k_count<<<EDGE4_BLKS, 256>>>(dst);
    cudaEventRecord(evI, 0);

    // Side stream: GEMM1 overlaps remaining CSR build
    cudaStreamWaitEvent(s2, evI, 0);
    k_gemm<<<GEMM_BLKS, 256, DSMEM_SZ, s2>>>(emb, 0);
    cudaEventRecord(evJ, s2);

    // Main stream: rest of CSR build
    k_scanA<<<SCAN_BLKS, 512>>>();
    k_scanB<<<1, 256>>>(SCAN_BLKS);
    k_scanC<<<SCAN_BLKS, 512>>>();
    k_place<<<EDGE4_BLKS, 256>>>(src, dst);

    // Join, then layer-1 agg -> layer-2 GEMM -> layer-2 agg + output proj
    cudaStreamWaitEvent(0, evJ, 0);
    k_agg<<<AGG_BLKS, 256>>>(0, b1, nullptr, nullptr, nullptr);
    k_gemm<<<GEMM_BLKS, 256, DSMEM_SZ>>>(nullptr, 1);
    k_agg<<<AGG_BLKS, 256>>>(1, b2, Wout, bout, out);
}